// round 13
// baseline (speedup 1.0000x reference)
#include <cuda_runtime.h>
#include <math_constants.h>

// PCEN: [B=32, T=4096, F=256] fp32.
//   ema_t = w*x_t + (1-w)*ema_{t-1},  ema_{-1} = x_0
//   v     = (x*(EPS+ema)^(-g) + bias)^(1/r) - bias^(1/r)
//   out   = 2*(v - min v)/(max v - min v) - 1   (global min/max)
//
// Round 12: half-split for L2 residency at FULL proven grid shape.
//  - L=64 chunks -> 262144 threads / 1024 blocks per pass per half
//    (exact R3 launch shape, the config that measured 5.4 TB/s).
//  - K1(h) K2(h) K3(h) per half: K3 re-reads its 67MB half L2-hot
//    (only 4MB of K2 in between; 67 < 126MB L2).
//  - K4(h1) right after K3(h1): h1 L2-hot for output. Only K4(h0) re-DRAMs.
//  - Bodies are R3's proven ones: __powf only (NO sqrtf — IEEE sqrt is slow
//    without fast-math, measured R11), unroll 4, branch-free.

#define EPSC 1e-6f
#define BB   32
#define TT   4096
#define FF   256
#define LL   64
#define NCHUNK (TT / LL)               // 64 chunks per chain
#define HALF_B (BB / 2)                // 16
#define NT_H   (HALF_B * NCHUNK * FF)  // 262144 threads per half
#define CH_H   (HALF_B * FF)           // 4096 chains per half

__device__ float    g_S[BB * NCHUNK * FF];  // chunk aggregates [(b,c,f)]
__device__ float    g_A[BB * NCHUNK * FF];  // chunk carry-ins  [(b,c,f)]
__device__ unsigned g_minmax[2];            // ordered-uint min/max keys of u

__device__ __forceinline__ unsigned f2key(float f) {
    unsigned u = __float_as_uint(f);
    return (u & 0x80000000u) ? ~u : (u | 0x80000000u);
}
__device__ __forceinline__ float key2f(unsigned k) {
    return __uint_as_float((k & 0x80000000u) ? (k & 0x7FFFFFFFu) : ~k);
}

// ---------------------------------------------------------------------------
// K1: per-chunk local scan with zero carry -> g_S. One B-half, full grid.
// tid: f = tid&255 (coalesced), c = (tid>>8)&63, b = b0 + (tid>>14).
// ---------------------------------------------------------------------------
__global__ void __launch_bounds__(256) k1_chunk_scan(
    const float* __restrict__ x, const float* __restrict__ smooth, int b0)
{
    int tid = blockIdx.x * blockDim.x + threadIdx.x;
    int f = tid & (FF - 1);
    int c = (tid >> 8) & (NCHUNK - 1);
    int b = b0 + (tid >> 14);

    float w   = fminf(fmaxf(smooth[0], 0.0f), 1.0f);
    float omw = 1.0f - w;

    const float* p = x + ((size_t)(b * TT + c * LL)) * FF + f;

    float a = 0.0f;
    #pragma unroll 8
    for (int i = 0; i < LL; i++) {
        a = fmaf(omw, a, w * p[(size_t)i * FF]);
    }
    g_S[(b * NCHUNK + c) * FF + f] = a;
}

// ---------------------------------------------------------------------------
// K2: per-chain sequential combine of 64 chunk carries -> g_A. One half.
// First half also resets g_minmax (stream-ordered, replay-safe).
// ---------------------------------------------------------------------------
__global__ void __launch_bounds__(256) k2_combine(
    const float* __restrict__ x, const float* __restrict__ smooth, int b0)
{
    int tid = blockIdx.x * blockDim.x + threadIdx.x;
    if (b0 == 0 && tid == 0) {
        g_minmax[0] = 0xFFFFFFFFu;  // min key (= +inf)
        g_minmax[1] = 0x00000000u;  // max key (= -inf)
    }
    if (tid >= CH_H) return;

    int f = tid & (FF - 1);
    int b = b0 + (tid >> 8);

    float w   = fminf(fmaxf(smooth[0], 0.0f), 1.0f);
    float omw = 1.0f - w;
    float D = omw;                  // omw^64 via 6 squarings (exact)
    #pragma unroll
    for (int i = 0; i < 6; i++) D *= D;

    float A = x[(size_t)b * TT * FF + f];   // ema_{-1} = x[b,0,f]
    int base = (b * NCHUNK) * FF + f;
    #pragma unroll 8
    for (int c = 0; c < NCHUNK; c++) {
        g_A[base + c * FF] = A;
        A = fmaf(D, A, g_S[base + c * FF]);
    }
}

// ---------------------------------------------------------------------------
// K3: rescan (L2-hot re-read) with true carry, reduce global min/max of
// u = x*(EPS+ema)^(-g). v is monotone in u (bias>0, 0<1/r<=1) so u suffices.
// ---------------------------------------------------------------------------
__global__ void __launch_bounds__(256) k3_minmax(
    const float* __restrict__ x,
    const float* __restrict__ gain, const float* __restrict__ smooth, int b0)
{
    int tid = blockIdx.x * blockDim.x + threadIdx.x;
    int f = tid & (FF - 1);
    int c = (tid >> 8) & (NCHUNK - 1);
    int b = b0 + (tid >> 14);

    float w   = fminf(fmaxf(smooth[0], 0.0f), 1.0f);
    float omw = 1.0f - w;
    float g   = fminf(gain[0], 1.0f);

    const float* p = x + ((size_t)(b * TT + c * LL)) * FF + f;

    float a  = g_A[(b * NCHUNK + c) * FF + f];
    float mn = CUDART_INF_F, mx = -CUDART_INF_F;

    #pragma unroll 4
    for (int i = 0; i < LL; i++) {
        float xv = p[(size_t)i * FF];
        a = fmaf(omw, a, w * xv);
        float u = xv * __powf(EPSC + a, -g);
        mn = fminf(mn, u);
        mx = fmaxf(mx, u);
    }

    #pragma unroll
    for (int o = 16; o; o >>= 1) {
        mn = fminf(mn, __shfl_xor_sync(0xFFFFFFFFu, mn, o));
        mx = fmaxf(mx, __shfl_xor_sync(0xFFFFFFFFu, mx, o));
    }
    __shared__ float smn[8], smx[8];
    int wid = threadIdx.x >> 5, lane = threadIdx.x & 31;
    if (lane == 0) { smn[wid] = mn; smx[wid] = mx; }
    __syncthreads();
    if (threadIdx.x == 0) {
        float bmn = smn[0], bmx = smx[0];
        #pragma unroll
        for (int i = 1; i < 8; i++) {
            bmn = fminf(bmn, smn[i]);
            bmx = fmaxf(bmx, smx[i]);
        }
        atomicMin(&g_minmax[0], f2key(bmn));
        atomicMax(&g_minmax[1], f2key(bmx));
    }
}

// ---------------------------------------------------------------------------
// K4: rescan, v' = (u+bias)^(1/r), normalize, write. bias^(1/r) cancels:
// out = (v' - v'min)*2/(v'max - v'min) - 1.
// vmn/vmx use the SAME __powf sequence as the loop body, so the extreme
// elements map exactly to -1/+1.
// ---------------------------------------------------------------------------
__global__ void __launch_bounds__(256) k4_output(
    const float* __restrict__ x, float* __restrict__ out,
    const float* __restrict__ gain, const float* __restrict__ bias,
    const float* __restrict__ root, const float* __restrict__ smooth, int b0)
{
    int tid = blockIdx.x * blockDim.x + threadIdx.x;
    int f = tid & (FF - 1);
    int c = (tid >> 8) & (NCHUNK - 1);
    int b = b0 + (tid >> 14);

    float w   = fminf(fmaxf(smooth[0], 0.0f), 1.0f);
    float omw = 1.0f - w;
    float g   = fminf(gain[0], 1.0f);
    float r   = fmaxf(root[0], 1.0f);
    float oor = 1.0f / r;
    float bs  = bias[0];

    float vmn = __powf(key2f(g_minmax[0]) + bs, oor);
    float vmx = __powf(key2f(g_minmax[1]) + bs, oor);
    float sc  = 2.0f / (vmx - vmn);

    size_t off = ((size_t)(b * TT + c * LL)) * FF + f;
    const float* p = x + off;
    float*       q = out + off;

    float a = g_A[(b * NCHUNK + c) * FF + f];

    #pragma unroll 4
    for (int i = 0; i < LL; i++) {
        float xv = p[(size_t)i * FF];
        a = fmaf(omw, a, w * xv);
        float u  = xv * __powf(EPSC + a, -g);
        float vp = __powf(u + bs, oor);
        q[(size_t)i * FF] = fmaf(vp - vmn, sc, -1.0f);
    }
}

extern "C" void kernel_launch(void* const* d_in, const int* in_sizes, int n_in,
                              void* d_out, int out_size)
{
    const float* x      = (const float*)d_in[0];
    const float* gain   = (const float*)d_in[1];
    const float* bias   = (const float*)d_in[2];
    const float* root   = (const float*)d_in[3];
    const float* smooth = (const float*)d_in[4];
    float* out = (float*)d_out;

    const int GK = NT_H / 256;           // 1024 blocks per half (= R3 shape)
    const int G2 = (CH_H + 255) / 256;   // 16 blocks for K2

    // half 0: scan -> combine -> minmax (x[h0] L2-hot for K3)
    k1_chunk_scan<<<GK, 256>>>(x, smooth, 0);
    k2_combine  <<<G2, 256>>>(x, smooth, 0);
    k3_minmax   <<<GK, 256>>>(x, gain, smooth, 0);
    // half 1
    k1_chunk_scan<<<GK, 256>>>(x, smooth, HALF_B);
    k2_combine  <<<G2, 256>>>(x, smooth, HALF_B);
    k3_minmax   <<<GK, 256>>>(x, gain, smooth, HALF_B);
    // output: h1 first (x[h1] still L2-hot), then h0
    k4_output   <<<GK, 256>>>(x, out, gain, bias, root, smooth, HALF_B);
    k4_output   <<<GK, 256>>>(x, out, gain, bias, root, smooth, 0);
}